// round 4
// baseline (speedup 1.0000x reference)
#include <cuda_runtime.h>
#include <cstdint>

// Problem constants (fixed by the reference)
#define BB   8
#define KK   100000
#define CC   16
#define OO   16
#define HH   512
#define WW   512
#define NNODES (BB * KK)
#define ALPHA_PRIOR 1.0f

#define TS     32                 // tile size (pixels per side)
#define NTX    (WW / TS)          // 16 tiles per row
#define NTILES (NTX * NTX)        // 256 tiles per batch
#define NBINS  (BB * NTILES)      // 2048 bins
#define CAP    1024               // bin capacity (mean ~440, deterministic input)

// Padded SMEM accumulator geometry: 34 halo rows x 36 padded cols, 16 channel planes
#define HROWS  34
#define HCOLS  36                 // 34 used + 2 pad (stride mult of 4 for float4)
#define PLANE  (HROWS * HCOLS)    // 1224 floats per channel
#define ACCF4  (OO * PLANE / 4)   // 4896 float4 to zero
#define SMEM_BYTES (OO * PLANE * 4)  // 78336 B

__device__ int      g_cnt[NBINS];
__device__ unsigned g_bin[(size_t)NBINS * CAP];

// ---------------------------------------------------------------------------
// Kernel 0: zero bin counters
// ---------------------------------------------------------------------------
__global__ void zero_cnt_kernel() {
    int i = blockIdx.x * 256 + threadIdx.x;
    if (i < NBINS) g_cnt[i] = 0;
}

// ---------------------------------------------------------------------------
// Kernel 1: bin nodes by tile (duplicating into halo-overlapping tiles).
// Entry pack: bits0-16 = node idx within batch, 17-22 = halo lx (0..33),
//             23-28 = halo ly, 29 = type.
// ---------------------------------------------------------------------------
__global__ __launch_bounds__(256) void bin_kernel(
    const float* __restrict__ node_xy,
    const int*   __restrict__ node_types)
{
    int n = blockIdx.x * 256 + threadIdx.x;
    if (n >= NNODES) return;
    int b  = n / KK;
    int nl = n - b * KK;

    float x = node_xy[2 * (size_t)n + 0];
    float y = node_xy[2 * (size_t)n + 1];
    int   t = node_types[n] & 1;

    // jnp.round == round-half-to-even == rintf; clip to [0, 511]
    int ix = (int)fminf(fmaxf(rintf(x), 0.f), (float)(WW - 1));
    int iy = (int)fminf(fmaxf(rintf(y), 0.f), (float)(HH - 1));

    int tx = ix >> 5, ty = iy >> 5;
    int lx = ix & 31, ly = iy & 31;

    // x-axis memberships: own tile (halo col lx+1); neighbor if on edge.
    int txs[2], lxs[2], nx = 1;
    txs[0] = tx; lxs[0] = lx + 1;
    if (lx == 0 && tx > 0)              { txs[1] = tx - 1; lxs[1] = 33; nx = 2; }
    else if (lx == 31 && tx < NTX - 1)  { txs[1] = tx + 1; lxs[1] = 0;  nx = 2; }

    int tys[2], lys[2], ny = 1;
    tys[0] = ty; lys[0] = ly + 1;
    if (ly == 0 && ty > 0)              { tys[1] = ty - 1; lys[1] = 33; ny = 2; }
    else if (ly == 31 && ty < NTX - 1)  { tys[1] = ty + 1; lys[1] = 0;  ny = 2; }

    for (int a = 0; a < ny; a++)
        for (int c = 0; c < nx; c++) {
            int bin = b * NTILES + tys[a] * NTX + txs[c];
            int slot = atomicAdd(&g_cnt[bin], 1);
            if (slot < CAP) {
                unsigned e = (unsigned)nl | ((unsigned)lxs[c] << 17)
                           | ((unsigned)lys[a] << 23) | ((unsigned)t << 29);
                g_bin[(size_t)bin * CAP + slot] = e;
            }
        }
}

// ---------------------------------------------------------------------------
// Kernel 2: per-tile splat + conv + writeout, entirely through SMEM.
// One block per (batch, tile): 2048 blocks, 256 threads, 78 KB dyn smem.
// ---------------------------------------------------------------------------
__device__ __forceinline__ float dot16(const float* w,
                                       float4 f0, float4 f1, float4 f2, float4 f3) {
    const float4* w4 = (const float4*)w;
    float4 w0 = w4[0], w1 = w4[1], w2 = w4[2], w3 = w4[3];
    return w0.x * f0.x + w0.y * f0.y + w0.z * f0.z + w0.w * f0.w
         + w1.x * f1.x + w1.y * f1.y + w1.z * f1.z + w1.w * f1.w
         + w2.x * f2.x + w2.y * f2.y + w2.z * f2.z + w2.w * f2.w
         + w3.x * f3.x + w3.y * f3.y + w3.z * f3.z + w3.w * f3.w;
}

__global__ __launch_bounds__(256) void tile_kernel(
    const float* __restrict__ node_feat,   // [B,K,C]
    const float* __restrict__ w_obj,       // [O,C]
    const float* __restrict__ w_prior,     // [O,C]
    float* __restrict__ out)               // [B,O,H,W]
{
    extern __shared__ float acc[];         // [16][PLANE] channel-major planes
    __shared__ float sw[2][OO * CC];

    int tid  = threadIdx.x;
    int bin  = blockIdx.x;                 // 0..2047
    int b    = bin >> 8;
    int tile = bin & 255;
    int ty   = tile >> 4, tx = tile & 15;

    // zero accumulator (incl. padding cols -> conv can over-read safely)
    float4* accv = (float4*)acc;
    for (int i = tid; i < ACCF4; i += 256)
        accv[i] = make_float4(0.f, 0.f, 0.f, 0.f);
    if (tid < OO * CC) {
        sw[0][tid] = w_obj[tid];
        sw[1][tid] = ALPHA_PRIOR * w_prior[tid];
    }
    __syncthreads();

    // ---- splat ----
    int cnt = g_cnt[bin];
    if (cnt > CAP) cnt = CAP;
    const unsigned* binp = &g_bin[(size_t)bin * CAP];

    for (int i = tid; i < cnt; i += 256) {
        unsigned e = binp[i];
        int nl  = e & 0x1FFFF;
        int lxh = (e >> 17) & 63;
        int lyh = (e >> 23) & 63;
        int t   = (e >> 29) & 1;

        const float4* f4 = (const float4*)(node_feat + ((size_t)b * KK + nl) * CC);
        float4 f0 = f4[0], f1 = f4[1], f2 = f4[2], f3 = f4[3];

        const float* wbase = sw[t];
        int pix = lyh * HCOLS + lxh;
        #pragma unroll
        for (int o = 0; o < 16; o++) {
            float v = dot16(wbase + o * CC, f0, f1, f2, f3);
            atomicAdd(&acc[o * PLANE + pix], v);
        }
    }
    __syncthreads();

    // ---- conv 3x3 + NCHW writeout ----
    // thread -> output row y (0..31) and x-quad q (0..7): 4 consecutive x.
    int y  = tid >> 3;
    int x0 = (tid & 7) * 4;

    int gy  = ty * TS + y;
    int gx0 = tx * TS + x0;
    const size_t plane_out = (size_t)HH * WW;
    size_t obase = (size_t)b * OO * plane_out + (size_t)gy * WW + gx0;

    #pragma unroll
    for (int o = 0; o < 16; o++) {
        const float* pl = acc + o * PLANE;
        float a0 = 0.f, a1 = 0.f, a2 = 0.f, a3 = 0.f;

        #pragma unroll
        for (int dy = 0; dy < 3; dy++) {
            int hr = y + dy;                       // halo row (0..33)
            const float* row = pl + hr * HCOLS + x0;
            float4 lo = *(const float4*)(row);     // halo cols x0..x0+3
            float4 hi = *(const float4*)(row + 4); // halo cols x0+4..x0+7 (pad=0 safe)
            float kl = (dy == 1) ? 0.125f : 0.075f;
            float kc = (dy == 1) ? 0.300f : 0.125f;
            // output j uses halo cols x0+j, x0+j+1, x0+j+2
            a0 += kl * (lo.x + lo.z) + kc * lo.y;
            a1 += kl * (lo.y + lo.w) + kc * lo.z;
            a2 += kl * (lo.z + hi.x) + kc * lo.w;
            a3 += kl * (lo.w + hi.y) + kc * hi.x;
        }
        float4 r = make_float4(a0, a1, a2, a3);
        *(float4*)(out + obase + (size_t)o * plane_out) = r;
    }
}

// ---------------------------------------------------------------------------
// Launch: zero counters -> bin -> tile. All big enough to fill the chip.
// Inputs: node_feat, node_xy, hw(int64, unused), node_types, w_obj, w_prior.
// ---------------------------------------------------------------------------
extern "C" void kernel_launch(void* const* d_in, const int* in_sizes, int n_in,
                              void* d_out, int out_size) {
    const float* node_feat  = (const float*)d_in[0];
    const float* node_xy    = (const float*)d_in[1];
    const int*   node_types = (const int*)d_in[3];
    const float* w_obj      = (const float*)d_in[4];
    const float* w_prior    = (const float*)d_in[5];
    float* out = (float*)d_out;

    static bool init = false;
    if (!init) {
        cudaFuncSetAttribute(tile_kernel,
                             cudaFuncAttributeMaxDynamicSharedMemorySize,
                             SMEM_BYTES);
        init = true;
    }

    zero_cnt_kernel<<<(NBINS + 255) / 256, 256>>>();
    bin_kernel<<<(NNODES + 255) / 256, 256>>>(node_xy, node_types);
    tile_kernel<<<NBINS, 256, SMEM_BYTES>>>(node_feat, w_obj, w_prior, out);
}

// round 5
// speedup vs baseline: 1.1404x; 1.1404x over previous
#include <cuda_runtime.h>
#include <cstdint>

// Problem constants (fixed by the reference)
#define BB   8
#define KK   100000
#define CC   16
#define OO   16
#define HH   512
#define WW   512
#define ALPHA_PRIOR 1.0f

#define NB4      4                          // batches per super-step
#define NSTEP    (BB / NB4)                 // 2 super-steps
#define NPIX_B   (HH * WW)                  // 262144 pixels per batch
#define GRID_F4  ((size_t)NPIX_B * 4)       // float4 per batch grid
#define NODES_STEP (NB4 * KK)               // 400000 nodes per super-step

// 4 one-batch scratch grids, [H, W, O] as float4 chunks. 67 MB -> L2-resident.
__device__ float4 g_grid[NB4][GRID_F4];

// ---------------------------------------------------------------------------
// Scatter: per-node channel transform + red.global into the NHWC batch grid.
// One super-step = 4 batches = 400k nodes -> 1563 blocks (fills the chip).
// ---------------------------------------------------------------------------
__device__ __forceinline__ float dot16(const float* w,
                                       float4 f0, float4 f1, float4 f2, float4 f3) {
    const float4* w4 = (const float4*)w;
    float4 w0 = w4[0], w1 = w4[1], w2 = w4[2], w3 = w4[3];
    return w0.x * f0.x + w0.y * f0.y + w0.z * f0.z + w0.w * f0.w
         + w1.x * f1.x + w1.y * f1.y + w1.z * f1.z + w1.w * f1.w
         + w2.x * f2.x + w2.y * f2.y + w2.z * f2.z + w2.w * f2.w
         + w3.x * f3.x + w3.y * f3.y + w3.z * f3.z + w3.w * f3.w;
}

__global__ __launch_bounds__(256) void scatter_kernel(
    const float* __restrict__ node_feat,   // [B,K,C]
    const float* __restrict__ node_xy,     // [B,K,2]
    const int*   __restrict__ node_types,  // [B,K]
    const float* __restrict__ w_obj,       // [O,C]
    const float* __restrict__ w_prior,     // [O,C]
    int step)
{
    __shared__ float sw[2][OO * CC];       // [type][o*16+c]
    int tid = threadIdx.x;
    if (tid < OO * CC) {
        sw[0][tid] = w_obj[tid];
        sw[1][tid] = ALPHA_PRIOR * w_prior[tid];
    }
    __syncthreads();

    int i = blockIdx.x * 256 + tid;        // node index within super-step
    if (i >= NODES_STEP) return;
    size_t n = (size_t)step * NODES_STEP + i;   // global node index
    int b   = (int)(n / KK);
    int buf = b - step * NB4;              // 0..3

    const float4* f4 = (const float4*)(node_feat + n * CC);
    float4 f0 = f4[0], f1 = f4[1], f2 = f4[2], f3 = f4[3];

    float x = node_xy[2 * n + 0];
    float y = node_xy[2 * n + 1];
    int   t = node_types[n] & 1;

    // jnp.round == round-half-to-even == rintf; clip to [0, 511]
    int ix = (int)fminf(fmaxf(rintf(x), 0.f), (float)(WW - 1));
    int iy = (int)fminf(fmaxf(rintf(y), 0.f), (float)(HH - 1));

    const float* wbase = sw[t];
    float4* dst = &g_grid[buf][((size_t)iy * WW + ix) * 4];

    #pragma unroll
    for (int g = 0; g < 4; g++) {
        float4 v;
        v.x = dot16(wbase + (g * 4 + 0) * CC, f0, f1, f2, f3);
        v.y = dot16(wbase + (g * 4 + 1) * CC, f0, f1, f2, f3);
        v.z = dot16(wbase + (g * 4 + 2) * CC, f0, f1, f2, f3);
        v.w = dot16(wbase + (g * 4 + 3) * CC, f0, f1, f2, f3);
        asm volatile("red.global.add.v4.f32 [%0], {%1, %2, %3, %4};"
                     :: "l"(dst + g), "f"(v.x), "f"(v.y), "f"(v.z), "f"(v.w)
                     : "memory");
    }
}

// ---------------------------------------------------------------------------
// Conv: depthwise 3x3 over the NHWC batch grid, NCHW writeout (evict-first).
// Each thread: one x column, strip of 4 y rows (6 rows read -> 1.5x ampl).
// grid = (4 xblocks, 128 ystrips, 4 batches) = 2048 blocks per super-step.
// ---------------------------------------------------------------------------
__global__ __launch_bounds__(128) void conv_kernel(float* __restrict__ out, int step) {
    int x   = blockIdx.x * 128 + threadIdx.x;  // 0..511
    int y0  = blockIdx.y * 4;                  // strip start
    int buf = blockIdx.z;                      // 0..3
    int b   = step * NB4 + buf;

    float acc[4][16];
    #pragma unroll
    for (int j = 0; j < 4; j++)
        #pragma unroll
        for (int i = 0; i < 16; i++) acc[j][i] = 0.f;

    const float4 z4 = make_float4(0.f, 0.f, 0.f, 0.f);
    const float4* grid = g_grid[buf];

    #pragma unroll
    for (int r = 0; r < 6; r++) {
        int yy = y0 - 1 + r;
        if ((unsigned)yy >= HH) continue;      // y zero-pad

        const float4* row = &grid[(size_t)yy * (WW * 4)];
        float4 c[4], l[4], rr[4];
        #pragma unroll
        for (int g = 0; g < 4; g++) {
            c[g]  = __ldg(&row[(size_t)x * 4 + g]);
            l[g]  = (x > 0)      ? __ldg(&row[(size_t)(x - 1) * 4 + g]) : z4;
            rr[g] = (x < WW - 1) ? __ldg(&row[(size_t)(x + 1) * 4 + g]) : z4;
        }

        float u[16], v[16];
        #pragma unroll
        for (int g = 0; g < 4; g++) {
            float sx = l[g].x + rr[g].x, sy = l[g].y + rr[g].y;
            float sz = l[g].z + rr[g].z, sw_ = l[g].w + rr[g].w;
            u[g*4+0] = 0.075f * sx  + 0.125f * c[g].x;
            u[g*4+1] = 0.075f * sy  + 0.125f * c[g].y;
            u[g*4+2] = 0.075f * sz  + 0.125f * c[g].z;
            u[g*4+3] = 0.075f * sw_ + 0.125f * c[g].w;
            v[g*4+0] = 0.125f * sx  + 0.300f * c[g].x;
            v[g*4+1] = 0.125f * sy  + 0.300f * c[g].y;
            v[g*4+2] = 0.125f * sz  + 0.300f * c[g].z;
            v[g*4+3] = 0.125f * sw_ + 0.300f * c[g].w;
        }

        #pragma unroll
        for (int j = 0; j < 4; j++) {
            int d = (r - 1) - j;               // input row offset from output row
            if (d == 0) {
                #pragma unroll
                for (int i = 0; i < 16; i++) acc[j][i] += v[i];
            } else if (d == 1 || d == -1) {
                #pragma unroll
                for (int i = 0; i < 16; i++) acc[j][i] += u[i];
            }
        }
    }

    // NCHW writeout (streaming / evict-first so the grid stays L2-resident)
    const size_t plane = (size_t)HH * WW;
    size_t base = (size_t)b * OO * plane + (size_t)y0 * WW + x;
    #pragma unroll
    for (int o = 0; o < 16; o++)
        #pragma unroll
        for (int j = 0; j < 4; j++)
            __stcs(&out[base + (size_t)o * plane + (size_t)j * WW], acc[j][o]);
}

// ---------------------------------------------------------------------------
// Launch: 2 super-steps x (memset, scatter, conv) on one stream.
// Inputs: node_feat, node_xy, hw(int64, unused), node_types, w_obj, w_prior.
// ---------------------------------------------------------------------------
extern "C" void kernel_launch(void* const* d_in, const int* in_sizes, int n_in,
                              void* d_out, int out_size) {
    const float* node_feat  = (const float*)d_in[0];
    const float* node_xy    = (const float*)d_in[1];
    const int*   node_types = (const int*)d_in[3];
    const float* w_obj      = (const float*)d_in[4];
    const float* w_prior    = (const float*)d_in[5];
    float* out = (float*)d_out;

    static void* grid_ptr = nullptr;
    if (!grid_ptr) cudaGetSymbolAddress(&grid_ptr, g_grid);

    const size_t grid_bytes = (size_t)NB4 * GRID_F4 * sizeof(float4);  // 67 MB
    dim3 conv_grid(WW / 128, HH / 4, NB4);     // 2048 blocks

    for (int step = 0; step < NSTEP; step++) {
        cudaMemsetAsync(grid_ptr, 0, grid_bytes, 0);
        scatter_kernel<<<(NODES_STEP + 255) / 256, 256>>>(
            node_feat, node_xy, node_types, w_obj, w_prior, step);
        conv_kernel<<<conv_grid, 128>>>(out, step);
    }
}

// round 6
// speedup vs baseline: 1.5720x; 1.3784x over previous
#include <cuda_runtime.h>
#include <cstdint>

// Problem constants (fixed by the reference)
#define BB   8
#define KK   100000
#define CC   16
#define OO   16
#define HH   512
#define WW   512
#define ALPHA_PRIOR 1.0f

#define NB4        4                        // batches per super-step
#define NSTEP      (BB / NB4)               // 2 super-steps
#define NPIX_B     (HH * WW)                // 262144 pixels per batch
#define NODES_STEP (NB4 * KK)               // 400000 nodes per super-step

// Scratch: group-planar layout  [buf][group][H][W]  of float4 (group = 4 channels).
// 4 bufs * 4 groups * 262144 float4 = 67 MB -> L2-resident within a super-step.
__device__ float4 g_grid[NB4][4][NPIX_B];

// ---------------------------------------------------------------------------
// Scatter: per-node 16x16 transform + red.global.v4 into 4 group planes.
// 400k nodes per super-step -> 1563 blocks.
// ---------------------------------------------------------------------------
__device__ __forceinline__ float dot16(const float* w,
                                       float4 f0, float4 f1, float4 f2, float4 f3) {
    const float4* w4 = (const float4*)w;
    float4 w0 = w4[0], w1 = w4[1], w2 = w4[2], w3 = w4[3];
    return w0.x * f0.x + w0.y * f0.y + w0.z * f0.z + w0.w * f0.w
         + w1.x * f1.x + w1.y * f1.y + w1.z * f1.z + w1.w * f1.w
         + w2.x * f2.x + w2.y * f2.y + w2.z * f2.z + w2.w * f2.w
         + w3.x * f3.x + w3.y * f3.y + w3.z * f3.z + w3.w * f3.w;
}

__global__ __launch_bounds__(256) void scatter_kernel(
    const float* __restrict__ node_feat,   // [B,K,C]
    const float* __restrict__ node_xy,     // [B,K,2]
    const int*   __restrict__ node_types,  // [B,K]
    const float* __restrict__ w_obj,       // [O,C]
    const float* __restrict__ w_prior,     // [O,C]
    int step)
{
    __shared__ float sw[2][OO * CC];       // [type][o*16+c]
    int tid = threadIdx.x;
    if (tid < OO * CC) {
        sw[0][tid] = w_obj[tid];
        sw[1][tid] = ALPHA_PRIOR * w_prior[tid];
    }
    __syncthreads();

    int i = blockIdx.x * 256 + tid;        // node index within super-step
    if (i >= NODES_STEP) return;
    size_t n = (size_t)step * NODES_STEP + i;   // global node index
    int buf = i / KK;                      // 0..3

    const float4* f4 = (const float4*)(node_feat + n * CC);
    float4 f0 = f4[0], f1 = f4[1], f2 = f4[2], f3 = f4[3];

    float x = node_xy[2 * n + 0];
    float y = node_xy[2 * n + 1];
    int   t = node_types[n] & 1;

    // jnp.round == round-half-to-even == rintf; clip to [0, 511]
    int ix = (int)fminf(fmaxf(rintf(x), 0.f), (float)(WW - 1));
    int iy = (int)fminf(fmaxf(rintf(y), 0.f), (float)(HH - 1));

    const float* wbase = sw[t];
    int pix = iy * WW + ix;

    #pragma unroll
    for (int g = 0; g < 4; g++) {
        float4 v;
        v.x = dot16(wbase + (g * 4 + 0) * CC, f0, f1, f2, f3);
        v.y = dot16(wbase + (g * 4 + 1) * CC, f0, f1, f2, f3);
        v.z = dot16(wbase + (g * 4 + 2) * CC, f0, f1, f2, f3);
        v.w = dot16(wbase + (g * 4 + 3) * CC, f0, f1, f2, f3);
        float4* dst = &g_grid[buf][g][pix];
        asm volatile("red.global.add.v4.f32 [%0], {%1, %2, %3, %4};"
                     :: "l"(dst), "f"(v.x), "f"(v.y), "f"(v.z), "f"(v.w)
                     : "memory");
    }
}

// ---------------------------------------------------------------------------
// Conv: depthwise 3x3 over group-planar grid, NCHW writeout.
// Warp = one group, 32 consecutive x (coalesced float4 loads).
// Thread: one (x, group), strip of 8 y rows (10 rows read -> 1.25x ampl).
// Block = 4 warps (all 4 groups, same 32-x span). Grid = (16, 64, 4).
// ---------------------------------------------------------------------------
__global__ __launch_bounds__(128) void conv_kernel(float* __restrict__ out, int step) {
    int lane = threadIdx.x & 31;
    int g    = threadIdx.x >> 5;               // 0..3 (channel quad)
    int x    = blockIdx.x * 32 + lane;         // 0..511
    int y0   = blockIdx.y * 8;                 // strip start
    int buf  = blockIdx.z;                     // 0..3
    int b    = step * NB4 + buf;

    const float4* plane = g_grid[buf][g];
    const float4 z4 = make_float4(0.f, 0.f, 0.f, 0.f);

    float4 acc[8];
    #pragma unroll
    for (int j = 0; j < 8; j++) acc[j] = z4;

    #pragma unroll
    for (int r = 0; r < 10; r++) {
        int yy = y0 - 1 + r;
        if ((unsigned)yy >= HH) continue;      // y zero-pad

        const float4* row = plane + (size_t)yy * WW;
        float4 c  = __ldg(row + x);
        float4 l  = (x > 0)      ? __ldg(row + x - 1) : z4;
        float4 rr = (x < WW - 1) ? __ldg(row + x + 1) : z4;

        float sx = l.x + rr.x, sy = l.y + rr.y, sz = l.z + rr.z, sw_ = l.w + rr.w;
        float4 u, v;                            // row-combo partials
        u.x = 0.075f * sx  + 0.125f * c.x;  v.x = 0.125f * sx  + 0.300f * c.x;
        u.y = 0.075f * sy  + 0.125f * c.y;  v.y = 0.125f * sy  + 0.300f * c.y;
        u.z = 0.075f * sz  + 0.125f * c.z;  v.z = 0.125f * sz  + 0.300f * c.z;
        u.w = 0.075f * sw_ + 0.125f * c.w;  v.w = 0.125f * sw_ + 0.300f * c.w;

        #pragma unroll
        for (int j = 0; j < 8; j++) {
            int d = (r - 1) - j;               // input row offset from output row
            if (d == 0) {
                acc[j].x += v.x; acc[j].y += v.y; acc[j].z += v.z; acc[j].w += v.w;
            } else if (d == 1 || d == -1) {
                acc[j].x += u.x; acc[j].y += u.y; acc[j].z += u.z; acc[j].w += u.w;
            }
        }
    }

    // NCHW writeout: channels o = 4g..4g+3. Warp-coalesced scalar stores.
    const size_t plane_out = (size_t)HH * WW;
    size_t base = ((size_t)b * OO + g * 4) * plane_out + (size_t)y0 * WW + x;
    #pragma unroll
    for (int j = 0; j < 8; j++) {
        __stcs(&out[base + 0 * plane_out + (size_t)j * WW], acc[j].x);
        __stcs(&out[base + 1 * plane_out + (size_t)j * WW], acc[j].y);
        __stcs(&out[base + 2 * plane_out + (size_t)j * WW], acc[j].z);
        __stcs(&out[base + 3 * plane_out + (size_t)j * WW], acc[j].w);
    }
}

// ---------------------------------------------------------------------------
// Launch: 2 super-steps x (memset, scatter, conv) on one stream.
// Inputs: node_feat, node_xy, hw(int64, unused), node_types, w_obj, w_prior.
// ---------------------------------------------------------------------------
extern "C" void kernel_launch(void* const* d_in, const int* in_sizes, int n_in,
                              void* d_out, int out_size) {
    const float* node_feat  = (const float*)d_in[0];
    const float* node_xy    = (const float*)d_in[1];
    const int*   node_types = (const int*)d_in[3];
    const float* w_obj      = (const float*)d_in[4];
    const float* w_prior    = (const float*)d_in[5];
    float* out = (float*)d_out;

    static void* grid_ptr = nullptr;
    if (!grid_ptr) cudaGetSymbolAddress(&grid_ptr, g_grid);

    const size_t grid_bytes = sizeof(float4) * (size_t)NB4 * 4 * NPIX_B;  // 67 MB
    dim3 conv_grid(WW / 32, HH / 8, NB4);      // (16, 64, 4) = 4096 blocks

    for (int step = 0; step < NSTEP; step++) {
        cudaMemsetAsync(grid_ptr, 0, grid_bytes, 0);
        scatter_kernel<<<(NODES_STEP + 255) / 256, 256>>>(
            node_feat, node_xy, node_types, w_obj, w_prior, step);
        conv_kernel<<<conv_grid, 128>>>(out, step);
    }
}